// round 8
// baseline (speedup 1.0000x reference)
#include <cuda_runtime.h>
#include <cuda_bf16.h>

// B=16, N_VEC=2048, N_DIM=32, N_W=4, N_HID=128, VOCAB=32000, N_CLASS=10

typedef unsigned long long u64;

__device__ __forceinline__ u64 fma2(u64 a, u64 b, u64 c) {
    u64 d;
    asm("fma.rn.f32x2 %0, %1, %2, %3;" : "=l"(d) : "l"(a), "l"(b), "l"(c));
    return d;
}
__device__ __forceinline__ u64 pack2(float lo, float hi) {
    u64 r;
    asm("mov.b64 %0, {%1, %2};" : "=l"(r) : "f"(lo), "f"(hi));
    return r;
}
__device__ __forceinline__ float2 unpack2(u64 v) {
    float2 f;
    asm("mov.b64 {%0, %1}, %2;" : "=f"(f.x), "=f"(f.y) : "l"(v));
    return f;
}

// ---------- scratch (device globals; allocation is forbidden) ----------
__device__ float g_X [16 * 2048 * 32];
__device__ float g_VA[16 * 2048 * 32];
__device__ float g_VB[16 * 2048 * 32];
__device__ float g_Upart[16 * 16 * 129 * 32];   // [b][chunk(16)][129][32] (row 128 = bias c)
__device__ float g_U[16 * 129 * 32];            // [b][129][32]
__device__ float g_partF[16 * 32 * 10];
__device__ unsigned g_tick;

// ---------- X = emb[data], with per-block int64/int32 detection ----------
__global__ __launch_bounds__(256) void k_gather(const int* __restrict__ d32,
                                                const float* __restrict__ emb) {
    __shared__ int s_is64;
    int tid = threadIdx.x;
    if (tid == 0) s_is64 = 1;
    __syncthreads();
    if (tid < 32) { if (d32[2 * tid + 1] != 0) s_is64 = 0; }
    __syncthreads();
    int t = blockIdx.x * 256 + tid;              // over 16*2048*8 float4s
    int row = t >> 3, q = t & 7;
    int idx = s_is64 ? d32[row * 2] : d32[row];
    float4 v = *reinterpret_cast<const float4*>(emb + (size_t)idx * 32 + q * 4);
    *reinterpret_cast<float4*>(g_X + (size_t)row * 32 + q * 4) = v;
}

// ---------- U partials: U[b] = fw2[layer] @ V[b], c[b] = fb2[layer] . V[b] ----------
// grid (16 K-chunks, 16 batch, 2 h-halves), 256 threads; thread tile 2h x 4d.
// Same K-split (16 chunks of 128) and partials layout as the 186.5us baseline;
// h-split only adds resident warps (2x) with zero extra partials traffic.
__global__ __launch_bounds__(256) void k_upart(const float* __restrict__ fw2,
                                               const float* __restrict__ fb2,
                                               int vin_sel, int layer) {
    __shared__ __align__(16) float VsT[32 * 130];   // [d][m], pad 130
    int b = blockIdx.y, ch = blockIdx.x, hs = blockIdx.z, tid = threadIdx.x;
    int m0 = ch * 128;
    const float* Vin = (vin_sel == 0) ? g_X : (vin_sel == 1 ? g_VA : g_VB);
    const float* vg = Vin + ((size_t)(b * 2048 + m0)) * 32;
#pragma unroll
    for (int it = 0; it < 16; ++it) {
        int t = tid + it * 256;                  // t = m*32 + d
        VsT[(t & 31) * 130 + (t >> 5)] = vg[t];
    }
    __syncthreads();

    int d0 = (tid & 7) * 4;
    int h0 = hs * 64 + (tid >> 3) * 2;           // 32 h-groups of 2 rows
    const float* w0 = fw2 + ((size_t)(layer * 128 + h0)) * 2048 + m0;

    u64 acc[2][4];
#pragma unroll
    for (int a = 0; a < 2; ++a)
#pragma unroll
        for (int c = 0; c < 4; ++c) acc[a][c] = 0ull;

#pragma unroll 8
    for (int m = 0; m < 64; ++m) {               // 2 K-elems per iter
        u64 va[4];
#pragma unroll
        for (int kd = 0; kd < 4; ++kd)
            va[kd] = *reinterpret_cast<const u64*>(VsT + (d0 + kd) * 130 + 2 * m);
#pragma unroll
        for (int kh = 0; kh < 2; ++kh) {
            u64 w = *reinterpret_cast<const u64*>(w0 + (size_t)kh * 2048 + 2 * m);
#pragma unroll
            for (int kd = 0; kd < 4; ++kd) acc[kh][kd] = fma2(w, va[kd], acc[kh][kd]);
        }
    }

    float* up = g_Upart + (((size_t)(b * 16 + ch)) * 129 + h0) * 32 + d0;
#pragma unroll
    for (int kh = 0; kh < 2; ++kh) {
        float2 s0 = unpack2(acc[kh][0]), s1 = unpack2(acc[kh][1]);
        float2 s2 = unpack2(acc[kh][2]), s3 = unpack2(acc[kh][3]);
        *reinterpret_cast<float4*>(up + (size_t)kh * 32) =
            make_float4(s0.x + s0.y, s1.x + s1.y, s2.x + s2.y, s3.x + s3.y);
    }

    if (hs == 0 && tid < 8) {                    // bias row c (h == 128)
        int db = tid * 4;
        const float* wb = fb2 + (size_t)layer * 2048 + m0;
        u64 a[4] = {0ull, 0ull, 0ull, 0ull};
        for (int m = 0; m < 64; ++m) {
            u64 w2 = *reinterpret_cast<const u64*>(wb + 2 * m);
#pragma unroll
            for (int k = 0; k < 4; ++k)
                a[k] = fma2(w2, *reinterpret_cast<const u64*>(VsT + (db + k) * 130 + 2 * m), a[k]);
        }
        float2 s0 = unpack2(a[0]), s1 = unpack2(a[1]), s2 = unpack2(a[2]), s3 = unpack2(a[3]);
        *reinterpret_cast<float4*>(g_Upart + (((size_t)(b * 16 + ch)) * 129 + 128) * 32 + db) =
            make_float4(s0.x + s0.y, s1.x + s1.y, s2.x + s2.y, s3.x + s3.y);
    }
}

// ---------- reduce split-K partials (vectorized, MLP=16) ----------
__global__ __launch_bounds__(256) void k_ured() {
    int idx = blockIdx.x * 256 + threadIdx.x;    // over 16*1032 float4s
    if (idx >= 16 * 1032) return;
    int b = idx / 1032, r4 = idx - b * 1032;
    const float4* base = reinterpret_cast<const float4*>(g_Upart) + (size_t)b * 16 * 1032 + r4;
    float4 s = make_float4(0.f, 0.f, 0.f, 0.f);
#pragma unroll
    for (int c = 0; c < 16; ++c) {
        float4 v = base[(size_t)c * 1032];
        s.x += v.x; s.y += v.y; s.z += v.z; s.w += v.w;
    }
    reinterpret_cast<float4*>(g_U)[(size_t)b * 1032 + r4] = s;
}

// ---------- fused: H = gelu(X @ fw1 + fb1); V' = H @ U + c ----------
// 32 rows/block, 128 threads, grid (64,16). H stored transposed [j][r] in smem.
// (byte-identical to the 186.5us baseline)
__global__ __launch_bounds__(128) void k_vupd(const float* __restrict__ fw1,
                                              const float* __restrict__ fb1,
                                              int vout_sel, int layer) {
    __shared__ __align__(16) float Xs[32 * 32];     // [r][d]
    __shared__ __align__(16) float Us[129 * 32];    // [j][d]
    __shared__ __align__(16) float HsT[128 * 34];   // [j][r], pad 34 (keeps 8B align)
    int b = blockIdx.y, n0 = blockIdx.x * 32, tid = threadIdx.x;

    const float* xg = g_X + ((size_t)(b * 2048 + n0)) * 32;
#pragma unroll
    for (int it = 0; it < 8; ++it) Xs[tid + it * 128] = xg[tid + it * 128];
    const float* Ug = g_U + (size_t)b * 4128;
#pragma unroll
    for (int it = 0; it < 32; ++it) Us[tid + it * 128] = Ug[tid + it * 128];
    if (tid < 32) Us[4096 + tid] = Ug[4096 + tid];
    __syncthreads();

    // phase 1: thread handles 2 adjacent columns (jA, jB) x 16 rows; f32x2 along d.
    {
        int jA = (tid & 63) * 2, jB = jA + 1;
        int half = tid >> 6;
        const float* wbase = fw1 + (size_t)layer * 4096;
        u64 wcA[16], wcB[16];
#pragma unroll
        for (int k = 0; k < 16; ++k) {
            float2 r0 = *reinterpret_cast<const float2*>(wbase + (2 * k) * 128 + jA);
            float2 r1 = *reinterpret_cast<const float2*>(wbase + (2 * k + 1) * 128 + jA);
            wcA[k] = pack2(r0.x, r1.x);
            wcB[k] = pack2(r0.y, r1.y);
        }
        float bjA = fb1[layer * 128 + jA], bjB = fb1[layer * 128 + jB];
        int rbase = half * 16;
#pragma unroll 2
        for (int rr = 0; rr < 16; ++rr) {
            int r = rbase + rr;
            const u64* xq = reinterpret_cast<const u64*>(Xs + r * 32);
            u64 aA = 0ull, aB = 0ull;
#pragma unroll
            for (int k = 0; k < 16; ++k) {
                u64 x = xq[k];
                aA = fma2(x, wcA[k], aA);
                aB = fma2(x, wcB[k], aB);
            }
            float2 sA = unpack2(aA), sB = unpack2(aB);
            float xA = sA.x + sA.y + bjA;
            float xB = sB.x + sB.y + bjB;
            HsT[jA * 34 + r] = 0.5f * xA * (1.0f + erff(xA * 0.70710678118654752f));
            HsT[jB * 34 + r] = 0.5f * xB * (1.0f + erff(xB * 0.70710678118654752f));
        }
    }
    __syncthreads();

    // phase 2: thread tile 2 rows x 4 cols; per j: LDS.64(H) + LDS.128(U) + 4 FFMA2.
    {
        int rt = tid >> 3, dt = tid & 7;
        int r0 = rt * 2, d0 = dt * 4;
        u64 a00 = 0ull, a01 = 0ull, a10 = 0ull, a11 = 0ull;
#pragma unroll 4
        for (int j = 0; j < 128; ++j) {
            float2 h2 = *reinterpret_cast<const float2*>(HsT + j * 34 + r0);
            ulonglong2 u = *reinterpret_cast<const ulonglong2*>(Us + j * 32 + d0);
            u64 h0 = pack2(h2.x, h2.x), h1 = pack2(h2.y, h2.y);
            a00 = fma2(h0, u.x, a00);
            a01 = fma2(h0, u.y, a01);
            a10 = fma2(h1, u.x, a10);
            a11 = fma2(h1, u.y, a11);
        }
        float* Vout = (vout_sel == 1) ? g_VA : g_VB;
        float4 c4 = *reinterpret_cast<const float4*>(Us + 128 * 32 + d0);
        float2 p00 = unpack2(a00), p01 = unpack2(a01);
        float2 p10 = unpack2(a10), p11 = unpack2(a11);
        *reinterpret_cast<float4*>(Vout + ((size_t)(b * 2048 + n0 + r0)) * 32 + d0) =
            make_float4(p00.x + c4.x, p00.y + c4.y, p01.x + c4.z, p01.y + c4.w);
        *reinterpret_cast<float4*>(Vout + ((size_t)(b * 2048 + n0 + r0 + 1)) * 32 + d0) =
            make_float4(p10.x + c4.x, p10.y + c4.y, p11.x + c4.z, p11.y + c4.w);
    }
}

// ---------- final projection, fused partial + completion (ticket) ----------
__global__ __launch_bounds__(256) void k_fproj(const float* __restrict__ Wf,
                                               const float* __restrict__ bf,
                                               float* __restrict__ out) {
    __shared__ float wsum[8][10];
    __shared__ int s_last;
    int b = blockIdx.y, ch = blockIdx.x, tid = threadIdx.x;
    int lane = tid & 31, w = tid >> 5;
    float acc[10];
#pragma unroll
    for (int c = 0; c < 10; ++c) acc[c] = 0.f;
    const float* Vb = g_VB + (size_t)b * 65536 + ch * 2048;
#pragma unroll
    for (int q = 0; q < 8; ++q) {
        int k = q * 256 + tid;
        float v = Vb[k];
        const float* wr = Wf + (size_t)(ch * 2048 + k) * 10;
#pragma unroll
        for (int c = 0; c < 10; ++c) acc[c] += v * wr[c];
    }
#pragma unroll
    for (int c = 0; c < 10; ++c) {
#pragma unroll
        for (int s = 16; s > 0; s >>= 1) acc[c] += __shfl_down_sync(0xffffffffu, acc[c], s);
        if (lane == 0) wsum[w][c] = acc[c];
    }
    __syncthreads();
    if (tid < 10) {
        float s = 0.f;
#pragma unroll
        for (int ww = 0; ww < 8; ++ww) s += wsum[ww][tid];
        g_partF[((size_t)(b * 32 + ch)) * 10 + tid] = s;
    }
    __threadfence();
    __syncthreads();
    if (tid == 0) {
        unsigned prev = atomicAdd(&g_tick, 1u);
        s_last = (prev == 511u) ? 1 : 0;
    }
    __syncthreads();
    if (s_last) {
        __threadfence();
        if (tid < 160) {
            int bb = tid / 10, c = tid % 10;
            float s = bf[c];
#pragma unroll
            for (int cc = 0; cc < 32; ++cc) s += g_partF[((size_t)(bb * 32 + cc)) * 10 + c];
            out[tid] = s;
        }
        if (tid == 0) g_tick = 0u;   // reset for next graph replay
    }
}

extern "C" void kernel_launch(void* const* d_in, const int* in_sizes, int n_in,
                              void* d_out, int out_size) {
    const int*   data = (const int*)  d_in[0];
    const float* emb  = (const float*)d_in[1];
    const float* fw1  = (const float*)d_in[2];
    const float* fb1  = (const float*)d_in[3];
    const float* fw2  = (const float*)d_in[4];
    const float* fb2  = (const float*)d_in[5];
    const float* Wf   = (const float*)d_in[6];
    const float* bf   = (const float*)d_in[7];
    float* out = (float*)d_out;

    k_gather<<<1024, 256>>>(data, emb);

    // layers i = 3,2,1,0 ; V ping-pong: X -> VA -> VB -> VA -> VB
    int vin = 0;
    for (int it = 0; it < 4; ++it) {
        int layer = 3 - it;
        int vout = (vin == 1) ? 2 : 1;
        k_upart<<<dim3(16, 16, 2), 256>>>(fw2, fb2, vin, layer);
        k_ured<<<65, 256>>>();
        k_vupd<<<dim3(64, 16), 128>>>(fw1, fb1, vout, layer);
        vin = vout;
    }

    k_fproj<<<dim3(32, 16), 256>>>(Wf, bf, out);
}

// round 9
// speedup vs baseline: 1.4239x; 1.4239x over previous
#include <cuda_runtime.h>
#include <cuda_bf16.h>

// B=16, N_VEC=2048, N_DIM=32, N_W=4, N_HID=128, VOCAB=32000, N_CLASS=10

typedef unsigned long long u64;

__device__ __forceinline__ u64 fma2(u64 a, u64 b, u64 c) {
    u64 d;
    asm("fma.rn.f32x2 %0, %1, %2, %3;" : "=l"(d) : "l"(a), "l"(b), "l"(c));
    return d;
}
__device__ __forceinline__ u64 pack2(float lo, float hi) {
    u64 r;
    asm("mov.b64 %0, {%1, %2};" : "=l"(r) : "f"(lo), "f"(hi));
    return r;
}
__device__ __forceinline__ float2 unpack2(u64 v) {
    float2 f;
    asm("mov.b64 {%0, %1}, %2;" : "=f"(f.x), "=f"(f.y) : "l"(v));
    return f;
}
__device__ __forceinline__ unsigned f2tf32(float x) {
    unsigned r;
    asm("cvt.rna.tf32.f32 %0, %1;" : "=r"(r) : "f"(x));
    return r;
}
__device__ __forceinline__ void mma_tf32(float* c, const unsigned* a, const unsigned* b) {
    asm volatile(
        "mma.sync.aligned.m16n8k8.row.col.f32.tf32.tf32.f32 "
        "{%0,%1,%2,%3}, {%4,%5,%6,%7}, {%8,%9}, {%0,%1,%2,%3};"
        : "+f"(c[0]), "+f"(c[1]), "+f"(c[2]), "+f"(c[3])
        : "r"(a[0]), "r"(a[1]), "r"(a[2]), "r"(a[3]), "r"(b[0]), "r"(b[1]));
}

// ---------- scratch (device globals; allocation is forbidden) ----------
__device__ float g_X [16 * 2048 * 32];
__device__ float g_VA[16 * 2048 * 32];
__device__ float g_VB[16 * 2048 * 32];
__device__ float g_Upart[16 * 16 * 129 * 32];   // [b][chunk(16)][129][32] (row 128 = bias c)
__device__ float g_U[16 * 129 * 32];            // [b][129][32]
__device__ float g_partF[16 * 32 * 10];
__device__ unsigned g_tick;

// ---------- X = emb[data], with per-block int64/int32 detection ----------
__global__ __launch_bounds__(256) void k_gather(const int* __restrict__ d32,
                                                const float* __restrict__ emb) {
    __shared__ int s_is64;
    int tid = threadIdx.x;
    if (tid == 0) s_is64 = 1;
    __syncthreads();
    if (tid < 32) { if (d32[2 * tid + 1] != 0) s_is64 = 0; }
    __syncthreads();
    int t = blockIdx.x * 256 + tid;
    int row = t >> 3, q = t & 7;
    int idx = s_is64 ? d32[row * 2] : d32[row];
    float4 v = *reinterpret_cast<const float4*>(emb + (size_t)idx * 32 + q * 4);
    *reinterpret_cast<float4*>(g_X + (size_t)row * 32 + q * 4) = v;
}

// ---------- U partials via TF32 tensor cores (3xTF32 compensation) ----------
// grid (16 K-chunks, 16 batch), 256 threads (8 warps).
// Block computes partial C[128h x 32d] = fw2[128h x 128m] * V[128m x 32d].
// Warp w: h-rows [16w, 16w+16); n-tiles 0..3; k-steps 0..15 (K=8 each).
__global__ __launch_bounds__(256) void k_upart(const float* __restrict__ fw2,
                                               const float* __restrict__ fb2,
                                               int vin_sel, int layer) {
    __shared__ unsigned Bh[128 * 40];   // V hi (tf32 bits), [m][d] stride 40
    __shared__ unsigned Bl[128 * 40];   // V lo
    __shared__ float   Sfb[128];
    int b = blockIdx.y, ch = blockIdx.x, tid = threadIdx.x;
    int m0 = ch * 128;
    const float* Vin = (vin_sel == 0) ? g_X : (vin_sel == 1 ? g_VA : g_VB);
    const float4* vg4 = reinterpret_cast<const float4*>(Vin + ((size_t)(b * 2048 + m0)) * 32);

#pragma unroll
    for (int it = 0; it < 4; ++it) {
        int t4 = tid + it * 256;                 // 1024 float4s = 128m x 32d
        int m = t4 >> 3, dq = (t4 & 7) * 4;
        float4 v = vg4[t4];
        unsigned* ph = Bh + m * 40 + dq;
        unsigned* pl = Bl + m * 40 + dq;
        unsigned h;
        h = f2tf32(v.x); ph[0] = h; pl[0] = f2tf32(v.x - __uint_as_float(h));
        h = f2tf32(v.y); ph[1] = h; pl[1] = f2tf32(v.y - __uint_as_float(h));
        h = f2tf32(v.z); ph[2] = h; pl[2] = f2tf32(v.z - __uint_as_float(h));
        h = f2tf32(v.w); ph[3] = h; pl[3] = f2tf32(v.w - __uint_as_float(h));
    }
    if (tid < 128) Sfb[tid] = fb2[(size_t)layer * 2048 + m0 + tid];
    __syncthreads();

    int w = tid >> 5, lane = tid & 31;
    int grp = lane >> 2, tig = lane & 3;
    const float* A0 = fw2 + ((size_t)(layer * 128 + w * 16 + grp)) * 2048 + m0;
    const float* A8 = A0 + (size_t)8 * 2048;

    float accM[4][4], accC[4][4];
#pragma unroll
    for (int nt = 0; nt < 4; ++nt)
#pragma unroll
        for (int i = 0; i < 4; ++i) { accM[nt][i] = 0.f; accC[nt][i] = 0.f; }

#pragma unroll 4
    for (int ks = 0; ks < 16; ++ks) {
        int c0 = ks * 8 + tig;
        float a0f = A0[c0], a1f = A8[c0], a2f = A0[c0 + 4], a3f = A8[c0 + 4];
        unsigned ah[4], al[4];
        ah[0] = f2tf32(a0f); al[0] = f2tf32(a0f - __uint_as_float(ah[0]));
        ah[1] = f2tf32(a1f); al[1] = f2tf32(a1f - __uint_as_float(ah[1]));
        ah[2] = f2tf32(a2f); al[2] = f2tf32(a2f - __uint_as_float(ah[2]));
        ah[3] = f2tf32(a3f); al[3] = f2tf32(a3f - __uint_as_float(ah[3]));
        const unsigned* rh0 = Bh + (ks * 8 + tig) * 40 + grp;
        const unsigned* rh4 = rh0 + 4 * 40;
        const unsigned* rl0 = Bl + (ks * 8 + tig) * 40 + grp;
        const unsigned* rl4 = rl0 + 4 * 40;
#pragma unroll
        for (int nt = 0; nt < 4; ++nt) {
            unsigned bh[2] = { rh0[nt * 8], rh4[nt * 8] };
            unsigned bl[2] = { rl0[nt * 8], rl4[nt * 8] };
            mma_tf32(accM[nt], ah, bh);
            mma_tf32(accC[nt], al, bh);
            mma_tf32(accC[nt], ah, bl);
        }
    }

    float* up = g_Upart + (((size_t)(b * 16 + ch)) * 129 + w * 16) * 32;
#pragma unroll
    for (int nt = 0; nt < 4; ++nt) {
        int d = nt * 8 + tig * 2;
        float2 r0 = make_float2(accM[nt][0] + accC[nt][0], accM[nt][1] + accC[nt][1]);
        float2 r1 = make_float2(accM[nt][2] + accC[nt][2], accM[nt][3] + accC[nt][3]);
        *reinterpret_cast<float2*>(up + grp * 32 + d) = r0;
        *reinterpret_cast<float2*>(up + (grp + 8) * 32 + d) = r1;
    }

    if (w == 0) {                                // bias row c (h == 128), lane = d
        float acc = 0.f;
#pragma unroll 8
        for (int m = 0; m < 128; ++m)
            acc += Sfb[m] * (__uint_as_float(Bh[m * 40 + lane]) +
                             __uint_as_float(Bl[m * 40 + lane]));
        g_Upart[(((size_t)(b * 16 + ch)) * 129 + 128) * 32 + lane] = acc;
    }
}

// ---------- reduce split-K partials (vectorized, MLP=16) ----------
__global__ __launch_bounds__(256) void k_ured() {
    int idx = blockIdx.x * 256 + threadIdx.x;    // over 16*1032 float4s
    if (idx >= 16 * 1032) return;
    int b = idx / 1032, r4 = idx - b * 1032;
    const float4* base = reinterpret_cast<const float4*>(g_Upart) + (size_t)b * 16 * 1032 + r4;
    float4 s = make_float4(0.f, 0.f, 0.f, 0.f);
#pragma unroll
    for (int c = 0; c < 16; ++c) {
        float4 v = base[(size_t)c * 1032];
        s.x += v.x; s.y += v.y; s.z += v.z; s.w += v.w;
    }
    reinterpret_cast<float4*>(g_U)[(size_t)b * 1032 + r4] = s;
}

// ---------- fused: H = gelu(X @ fw1 + fb1); V' = H @ U + c ----------
// (byte-identical to the 186.5us baseline)
__global__ __launch_bounds__(128) void k_vupd(const float* __restrict__ fw1,
                                              const float* __restrict__ fb1,
                                              int vout_sel, int layer) {
    __shared__ __align__(16) float Xs[32 * 32];
    __shared__ __align__(16) float Us[129 * 32];
    __shared__ __align__(16) float HsT[128 * 34];
    int b = blockIdx.y, n0 = blockIdx.x * 32, tid = threadIdx.x;

    const float* xg = g_X + ((size_t)(b * 2048 + n0)) * 32;
#pragma unroll
    for (int it = 0; it < 8; ++it) Xs[tid + it * 128] = xg[tid + it * 128];
    const float* Ug = g_U + (size_t)b * 4128;
#pragma unroll
    for (int it = 0; it < 32; ++it) Us[tid + it * 128] = Ug[tid + it * 128];
    if (tid < 32) Us[4096 + tid] = Ug[4096 + tid];
    __syncthreads();

    {
        int jA = (tid & 63) * 2, jB = jA + 1;
        int half = tid >> 6;
        const float* wbase = fw1 + (size_t)layer * 4096;
        u64 wcA[16], wcB[16];
#pragma unroll
        for (int k = 0; k < 16; ++k) {
            float2 r0 = *reinterpret_cast<const float2*>(wbase + (2 * k) * 128 + jA);
            float2 r1 = *reinterpret_cast<const float2*>(wbase + (2 * k + 1) * 128 + jA);
            wcA[k] = pack2(r0.x, r1.x);
            wcB[k] = pack2(r0.y, r1.y);
        }
        float bjA = fb1[layer * 128 + jA], bjB = fb1[layer * 128 + jB];
        int rbase = half * 16;
#pragma unroll 2
        for (int rr = 0; rr < 16; ++rr) {
            int r = rbase + rr;
            const u64* xq = reinterpret_cast<const u64*>(Xs + r * 32);
            u64 aA = 0ull, aB = 0ull;
#pragma unroll
            for (int k = 0; k < 16; ++k) {
                u64 x = xq[k];
                aA = fma2(x, wcA[k], aA);
                aB = fma2(x, wcB[k], aB);
            }
            float2 sA = unpack2(aA), sB = unpack2(aB);
            float xA = sA.x + sA.y + bjA;
            float xB = sB.x + sB.y + bjB;
            HsT[jA * 34 + r] = 0.5f * xA * (1.0f + erff(xA * 0.70710678118654752f));
            HsT[jB * 34 + r] = 0.5f * xB * (1.0f + erff(xB * 0.70710678118654752f));
        }
    }
    __syncthreads();

    {
        int rt = tid >> 3, dt = tid & 7;
        int r0 = rt * 2, d0 = dt * 4;
        u64 a00 = 0ull, a01 = 0ull, a10 = 0ull, a11 = 0ull;
#pragma unroll 4
        for (int j = 0; j < 128; ++j) {
            float2 h2 = *reinterpret_cast<const float2*>(HsT + j * 34 + r0);
            ulonglong2 u = *reinterpret_cast<const ulonglong2*>(Us + j * 32 + d0);
            u64 h0 = pack2(h2.x, h2.x), h1 = pack2(h2.y, h2.y);
            a00 = fma2(h0, u.x, a00);
            a01 = fma2(h0, u.y, a01);
            a10 = fma2(h1, u.x, a10);
            a11 = fma2(h1, u.y, a11);
        }
        float* Vout = (vout_sel == 1) ? g_VA : g_VB;
        float4 c4 = *reinterpret_cast<const float4*>(Us + 128 * 32 + d0);
        float2 p00 = unpack2(a00), p01 = unpack2(a01);
        float2 p10 = unpack2(a10), p11 = unpack2(a11);
        *reinterpret_cast<float4*>(Vout + ((size_t)(b * 2048 + n0 + r0)) * 32 + d0) =
            make_float4(p00.x + c4.x, p00.y + c4.y, p01.x + c4.z, p01.y + c4.w);
        *reinterpret_cast<float4*>(Vout + ((size_t)(b * 2048 + n0 + r0 + 1)) * 32 + d0) =
            make_float4(p10.x + c4.x, p10.y + c4.y, p11.x + c4.z, p11.y + c4.w);
    }
}

// ---------- final projection, fused partial + completion (ticket) ----------
__global__ __launch_bounds__(256) void k_fproj(const float* __restrict__ Wf,
                                               const float* __restrict__ bf,
                                               float* __restrict__ out) {
    __shared__ float wsum[8][10];
    __shared__ int s_last;
    int b = blockIdx.y, ch = blockIdx.x, tid = threadIdx.x;
    int lane = tid & 31, w = tid >> 5;
    float acc[10];
#pragma unroll
    for (int c = 0; c < 10; ++c) acc[c] = 0.f;
    const float* Vb = g_VB + (size_t)b * 65536 + ch * 2048;
#pragma unroll
    for (int q = 0; q < 8; ++q) {
        int k = q * 256 + tid;
        float v = Vb[k];
        const float* wr = Wf + (size_t)(ch * 2048 + k) * 10;
#pragma unroll
        for (int c = 0; c < 10; ++c) acc[c] += v * wr[c];
    }
#pragma unroll
    for (int c = 0; c < 10; ++c) {
#pragma unroll
        for (int s = 16; s > 0; s >>= 1) acc[c] += __shfl_down_sync(0xffffffffu, acc[c], s);
        if (lane == 0) wsum[w][c] = acc[c];
    }
    __syncthreads();
    if (tid < 10) {
        float s = 0.f;
#pragma unroll
        for (int ww = 0; ww < 8; ++ww) s += wsum[ww][tid];
        g_partF[((size_t)(b * 32 + ch)) * 10 + tid] = s;
    }
    __threadfence();
    __syncthreads();
    if (tid == 0) {
        unsigned prev = atomicAdd(&g_tick, 1u);
        s_last = (prev == 511u) ? 1 : 0;
    }
    __syncthreads();
    if (s_last) {
        __threadfence();
        if (tid < 160) {
            int bb = tid / 10, c = tid % 10;
            float s = bf[c];
#pragma unroll
            for (int cc = 0; cc < 32; ++cc) s += g_partF[((size_t)(bb * 32 + cc)) * 10 + c];
            out[tid] = s;
        }
        if (tid == 0) g_tick = 0u;
    }
}

extern "C" void kernel_launch(void* const* d_in, const int* in_sizes, int n_in,
                              void* d_out, int out_size) {
    const int*   data = (const int*)  d_in[0];
    const float* emb  = (const float*)d_in[1];
    const float* fw1  = (const float*)d_in[2];
    const float* fb1  = (const float*)d_in[3];
    const float* fw2  = (const float*)d_in[4];
    const float* fb2  = (const float*)d_in[5];
    const float* Wf   = (const float*)d_in[6];
    const float* bf   = (const float*)d_in[7];
    float* out = (float*)d_out;

    k_gather<<<1024, 256>>>(data, emb);

    // layers i = 3,2,1,0 ; V ping-pong: X -> VA -> VB -> VA -> VB
    int vin = 0;
    for (int it = 0; it < 4; ++it) {
        int layer = 3 - it;
        int vout = (vin == 1) ? 2 : 1;
        k_upart<<<dim3(16, 16), 256>>>(fw2, fb2, vin, layer);
        k_ured<<<65, 256>>>();
        k_vupd<<<dim3(64, 16), 128>>>(fw1, fb1, vout, layer);
        vin = vout;
    }

    k_fproj<<<dim3(32, 16), 256>>>(Wf, bf, out);
}